// round 14
// baseline (speedup 1.0000x reference)
#include <cuda_runtime.h>
#include <cuda_fp16.h>

#define N_USER   100000
#define N_ITEM   100000
#define N_NODE2  200000          // combined dst space: [0,100K)=item(u2i), [100K,200K)=user(i2u)
#define N_EDGE   1600000
#define N_EDGE2  3200000
#define IN_DIM   128
#define OUT_DIM  64
#define NEG_SLOPE 0.01f
#define LROWS    32
#define NBLK_SCAN 196            // ceil(200000/1024)

// ---------------- device scratch (static, no runtime alloc) ----------------
__device__ __half2 g_Wh_user[(size_t)N_USER * 32];   // 12.8 MB
__device__ __half2 g_Wh_item[(size_t)N_ITEM * 32];   // 12.8 MB
__device__ float  g_su_src[N_USER];
__device__ float  g_su_dst[N_USER];
__device__ float  g_si_src[N_ITEM];
__device__ float  g_si_dst[N_ITEM];
__device__ int    g_cnt[N_NODE2];
__device__ int    g_offs[N_NODE2];
__device__ int    g_cursor[N_NODE2];
__device__ int    g_bsum[NBLK_SCAN];
__device__ int    g_boff[NBLK_SCAN];
__device__ float2 g_csr[N_EDGE2];     // packed (src_as_float, ex), 25.6 MB

// ---------------- per-replay reset: degree counters ----------------
__global__ __launch_bounds__(256) void zero_kernel(int* __restrict__ cnt)
{
    int i = blockIdx.x * blockDim.x + threadIdx.x;
    if (i < N_NODE2) cnt[i] = 0;
}

// ------- Wh = feat @ W + b fused with s_src/s_dst epilogue -------
// (measured-best inner loop: thread = 2 cols x 4 rows; fp16 output store)
__global__ __launch_bounds__(256) void linear_attn_kernel(
    const float* __restrict__ feat, const float* __restrict__ W,
    const float* __restrict__ b, const float* __restrict__ attn,
    __half2* __restrict__ Whh, float* __restrict__ s_src, float* __restrict__ s_dst)
{
    __shared__ float Ws[IN_DIM * OUT_DIM];   // 32 KB
    __shared__ float fs[LROWS][IN_DIM];      // 16 KB (reused for Wh tile)
    int tid = threadIdx.x;

    #pragma unroll
    for (int i = tid; i < IN_DIM * OUT_DIM; i += 256) Ws[i] = W[i];

    int row0 = blockIdx.x * LROWS;
    const float4* fsrc = reinterpret_cast<const float4*>(feat + (size_t)row0 * IN_DIM);
    float4* fdst = reinterpret_cast<float4*>(&fs[0][0]);
    #pragma unroll
    for (int i = tid; i < LROWS * IN_DIM / 4; i += 256) fdst[i] = fsrc[i];
    __syncthreads();

    int cg = tid & 31;   // column pair index
    int rg = tid >> 5;   // row group (4 rows)
    const float2* Ws2 = reinterpret_cast<const float2*>(Ws);
    float2 acc[4] = {{0.f,0.f},{0.f,0.f},{0.f,0.f},{0.f,0.f}};

    #pragma unroll 8
    for (int k = 0; k < IN_DIM; k++) {
        float2 w = Ws2[k * 32 + cg];
        #pragma unroll
        for (int r = 0; r < 4; r++) {
            float f = fs[rg * 4 + r][k];
            acc[r].x = fmaf(f, w.x, acc[r].x);
            acc[r].y = fmaf(f, w.y, acc[r].y);
        }
    }

    float2 b2 = reinterpret_cast<const float2*>(b)[cg];
    __syncthreads();   // done reading fs; reuse as Wh tile
    float2* sWh2 = reinterpret_cast<float2*>(&fs[0][0]);   // [32][32] float2
    #pragma unroll
    for (int r = 0; r < 4; r++) {
        acc[r].x += b2.x; acc[r].y += b2.y;
        int row = rg * 4 + r;
        Whh[(size_t)(row0 + row) * 32 + cg] = __float22half2_rn(acc[r]);
        sWh2[row * 32 + cg] = acc[r];
    }
    __syncthreads();

    // epilogue: 8 warps x 4 rows (fp32 tile — full precision for scalars)
    int wid = tid >> 5, lane = tid & 31;
    float a0 = attn[lane],      a1 = attn[lane + 32];
    float c0 = attn[64 + lane], c1 = attn[96 + lane];
    const float* sWh = &fs[0][0];
    #pragma unroll
    for (int rr = 0; rr < 4; rr++) {
        int row = wid * 4 + rr;
        float v0 = sWh[row * 64 + lane];
        float v1 = sWh[row * 64 + lane + 32];
        float ps = fmaf(v0, a0, v1 * a1);
        float pd = fmaf(v0, c0, v1 * c1);
        #pragma unroll
        for (int o = 16; o; o >>= 1) {
            ps += __shfl_xor_sync(0xffffffffu, ps, o);
            pd += __shfl_xor_sync(0xffffffffu, pd, o);
        }
        if (lane == 0) { s_src[row0 + row] = ps; s_dst[row0 + row] = pd; }
    }
}

// ---------------- histogram of dst degrees, both etypes (4 edges/thread) ----
__global__ __launch_bounds__(256) void hist_kernel(const int4* __restrict__ dstA4,
                                                   const int4* __restrict__ dstB4,
                                                   int* __restrict__ cnt)
{
    int i = blockIdx.x * blockDim.x + threadIdx.x;
    const int nq = N_EDGE / 4;
    if (i >= 2 * nq) return;
    bool second = i >= nq;
    int4 d = second ? dstB4[i - nq] : dstA4[i];
    int gbase = second ? N_ITEM : 0;
    atomicAdd(&cnt[gbase + d.x], 1);
    atomicAdd(&cnt[gbase + d.y], 1);
    atomicAdd(&cnt[gbase + d.z], 1);
    atomicAdd(&cnt[gbase + d.w], 1);
}

// ---------------- exclusive scan (3 kernels) ----------------
__global__ __launch_bounds__(256) void scan1_kernel(const int* __restrict__ cnt,
        int* __restrict__ offs, int* __restrict__ bsum)
{
    __shared__ int wsum[8];
    int tid = threadIdx.x;
    int base = blockIdx.x * 1024 + tid * 4;
    int v[4];
    #pragma unroll
    for (int q = 0; q < 4; q++) { int i = base + q; v[q] = (i < N_NODE2) ? cnt[i] : 0; }
    int t = v[0] + v[1] + v[2] + v[3];
    int lane = tid & 31, wid = tid >> 5;
    int inc = t;
    #pragma unroll
    for (int o = 1; o < 32; o <<= 1) { int n = __shfl_up_sync(0xffffffffu, inc, o); if (lane >= o) inc += n; }
    if (lane == 31) wsum[wid] = inc;
    __syncthreads();
    if (wid == 0) {
        int ws = (lane < 8) ? wsum[lane] : 0;
        int winc = ws;
        #pragma unroll
        for (int o = 1; o < 8; o <<= 1) { int n = __shfl_up_sync(0xffffffffu, winc, o); if (lane >= o) winc += n; }
        if (lane < 8) wsum[lane] = winc - ws;          // exclusive warp offsets
        if (lane == 7) bsum[blockIdx.x] = winc;        // block total
    }
    __syncthreads();
    int run = wsum[wid] + (inc - t);
    #pragma unroll
    for (int q = 0; q < 4; q++) { int i = base + q; if (i < N_NODE2) offs[i] = run; run += v[q]; }
}

__global__ __launch_bounds__(256) void scan2_kernel(const int* __restrict__ bsum,
                                                    int* __restrict__ boff)
{
    __shared__ int wsum[8];
    int tid = threadIdx.x;
    int v = (tid < NBLK_SCAN) ? bsum[tid] : 0;
    int lane = tid & 31, wid = tid >> 5;
    int inc = v;
    #pragma unroll
    for (int o = 1; o < 32; o <<= 1) { int n = __shfl_up_sync(0xffffffffu, inc, o); if (lane >= o) inc += n; }
    if (lane == 31) wsum[wid] = inc;
    __syncthreads();
    if (wid == 0) {
        int ws = (lane < 8) ? wsum[lane] : 0;
        int winc = ws;
        #pragma unroll
        for (int o = 1; o < 8; o <<= 1) { int n = __shfl_up_sync(0xffffffffu, winc, o); if (lane >= o) winc += n; }
        if (lane < 8) wsum[lane] = winc - ws;
    }
    __syncthreads();
    if (tid < NBLK_SCAN) boff[tid] = wsum[wid] + (inc - v);
}

__global__ __launch_bounds__(256) void scan3_kernel(int* __restrict__ offs,
        const int* __restrict__ boff, int* __restrict__ cursor)
{
    int i = blockIdx.x * blockDim.x + threadIdx.x;
    if (i >= N_NODE2) return;
    int o = offs[i] + boff[i >> 10];
    offs[i] = o;
    cursor[i] = o;
}

// --------- scatter (both etypes, 2 edges/thread): csr[pos] = (src, ex) ---------
__global__ __launch_bounds__(256) void scatter_kernel(
    const int2* __restrict__ srcA2, const int2* __restrict__ dstA2,
    const int2* __restrict__ srcB2, const int2* __restrict__ dstB2,
    const float* __restrict__ su_src, const float* __restrict__ su_dst,
    const float* __restrict__ si_src, const float* __restrict__ si_dst,
    int* __restrict__ cursor, float2* __restrict__ csr)
{
    int t = blockIdx.x * blockDim.x + threadIdx.x;
    const int nh = N_EDGE / 2;
    if (t >= 2 * nh) return;
    bool second = t >= nh;
    int e2 = second ? t - nh : t;
    int2 s2 = second ? srcB2[e2] : srcA2[e2];
    int2 d2 = second ? dstB2[e2] : dstA2[e2];
    const float* ssrc = second ? si_src : su_src;
    const float* sdst = second ? su_dst : si_dst;
    int gbase = second ? N_ITEM : 0;

    float vs0 = ssrc[s2.x], vs1 = ssrc[s2.y];
    float vd0 = sdst[d2.x], vd1 = sdst[d2.y];
    float v0 = vs0 + vd0;  v0 = v0 > 0.f ? v0 : NEG_SLOPE * v0;
    float v1 = vs1 + vd1;  v1 = v1 > 0.f ? v1 : NEG_SLOPE * v1;
    float ex0 = __expf(v0), ex1 = __expf(v1);

    int pos0 = atomicAdd(&cursor[gbase + d2.x], 1);
    int pos1 = atomicAdd(&cursor[gbase + d2.y], 1);
    csr[pos0] = make_float2(__int_as_float(s2.x), ex0);
    csr[pos1] = make_float2(__int_as_float(s2.y), ex1);
}

// --------- aggregate: warp per NODE PAIR; two interleaved CSR streams --------
// agg is latency-bound (fp16 byte-halving was neutral): one node/warp gives
// only 8 gathers in flight around a ~250cyc L2 latency. Two adjacent nodes per
// warp -> 16 independent gathers per batch + per-warp fixed costs amortized.
// N_ITEM is even, so a pair never straddles the item/user halves.
__global__ __launch_bounds__(256) void agg_kernel(
    const int* __restrict__ offs, const float2* __restrict__ csr,
    const __half2* __restrict__ Whu, const __half2* __restrict__ Whi,
    float2* __restrict__ out2)
{
    int pair = (blockIdx.x * 256 + threadIdx.x) >> 5;
    int lane = threadIdx.x & 31;
    if (pair >= N_NODE2 / 2) return;
    int g0 = pair * 2;
    int g1 = g0 + 1;

    int beg0 = offs[g0];
    int beg1 = offs[g1];            // == end0
    int end1 = (g1 == N_NODE2 - 1) ? N_EDGE2 : offs[g1 + 1];
    int len0 = beg1 - beg0;
    int len1 = end1 - beg1;

    const __half2* Wh2 = (g0 < N_ITEM) ? Whu : Whi;            // item-dst <- user src
    int orow0 = (g0 < N_ITEM) ? (N_USER + g0) : (g0 - N_ITEM);
    int orow1 = orow0 + 1;

    float2 acc0 = make_float2(0.f, 0.f), acc1 = make_float2(0.f, 0.f);
    float den0 = 0.f, den1 = 0.f;

    int nloop = len0 > len1 ? len0 : len1;
    for (int k0 = 0; k0 < nloop; k0 += 32) {
        int k = k0 + lane;
        float2 p0 = (k < len0) ? csr[beg0 + k] : make_float2(0.f, 0.f);
        float2 p1 = (k < len1) ? csr[beg1 + k] : make_float2(0.f, 0.f);
        int s0 = __float_as_int(p0.x); float e0 = p0.y;
        int s1 = __float_as_int(p1.x); float e1 = p1.y;
        int m = nloop - k0; if (m > 32) m = 32;
        for (int j0 = 0; j0 < m; j0 += 8) {
            #pragma unroll
            for (int jj = 0; jj < 8; jj++) {
                int   sa = __shfl_sync(0xffffffffu, s0, j0 + jj);
                float ea = __shfl_sync(0xffffffffu, e0, j0 + jj);
                int   sb = __shfl_sync(0xffffffffu, s1, j0 + jj);
                float eb = __shfl_sync(0xffffffffu, e1, j0 + jj);
                if (ea != 0.f) {
                    float2 z = __half22float2(Wh2[(size_t)sa * 32 + lane]);
                    acc0.x = fmaf(ea, z.x, acc0.x);
                    acc0.y = fmaf(ea, z.y, acc0.y);
                    den0 += ea;
                }
                if (eb != 0.f) {
                    float2 z = __half22float2(Wh2[(size_t)sb * 32 + lane]);
                    acc1.x = fmaf(eb, z.x, acc1.x);
                    acc1.y = fmaf(eb, z.y, acc1.y);
                    den1 += eb;
                }
            }
        }
    }
    if (len0 > 0) { float inv = 1.f / den0; acc0.x *= inv; acc0.y *= inv; }
    if (len1 > 0) { float inv = 1.f / den1; acc1.x *= inv; acc1.y *= inv; }
    out2[(size_t)orow0 * 32 + lane] = acc0;
    out2[(size_t)orow1 * 32 + lane] = acc1;
}

// ---------------- launch: forked-capture schedule (measured-best) ----------------
extern "C" void kernel_launch(void* const* d_in, const int* in_sizes, int n_in,
                              void* d_out, int out_size)
{
    const float* feat_user = (const float*)d_in[0];
    const float* feat_item = (const float*)d_in[1];
    const float* W_user    = (const float*)d_in[2];
    const float* b_user    = (const float*)d_in[3];
    const float* W_item    = (const float*)d_in[4];
    const float* b_item    = (const float*)d_in[5];
    const float* attn_w    = (const float*)d_in[6];
    const int*   src_u2i   = (const int*)d_in[7];
    const int*   dst_u2i   = (const int*)d_in[8];
    const int*   src_i2u   = (const int*)d_in[9];
    const int*   dst_i2u   = (const int*)d_in[10];
    float* out = (float*)d_out;

    // true DEVICE addresses of __device__ globals (host-shadow/ATS trap!)
    __half2 *Wh_user, *Wh_item;
    float *su_src, *su_dst, *si_src, *si_dst;
    float2 *csr;
    int *cnt, *offs, *cursor, *bsum, *boff;
    cudaGetSymbolAddress((void**)&Wh_user, g_Wh_user);
    cudaGetSymbolAddress((void**)&Wh_item, g_Wh_item);
    cudaGetSymbolAddress((void**)&su_src,  g_su_src);
    cudaGetSymbolAddress((void**)&su_dst,  g_su_dst);
    cudaGetSymbolAddress((void**)&si_src,  g_si_src);
    cudaGetSymbolAddress((void**)&si_dst,  g_si_dst);
    cudaGetSymbolAddress((void**)&cnt,     g_cnt);
    cudaGetSymbolAddress((void**)&offs,    g_offs);
    cudaGetSymbolAddress((void**)&cursor,  g_cursor);
    cudaGetSymbolAddress((void**)&bsum,    g_bsum);
    cudaGetSymbolAddress((void**)&boff,    g_boff);
    cudaGetSymbolAddress((void**)&csr,     g_csr);

    static cudaStream_t sB = nullptr, sC = nullptr;
    static cudaEvent_t ev0 = nullptr, evB = nullptr, evC = nullptr;
    if (sB == nullptr) {
        cudaStreamCreateWithFlags(&sB, cudaStreamNonBlocking);
        cudaStreamCreateWithFlags(&sC, cudaStreamNonBlocking);
        cudaEventCreateWithFlags(&ev0, cudaEventDisableTiming);
        cudaEventCreateWithFlags(&evB, cudaEventDisableTiming);
        cudaEventCreateWithFlags(&evC, cudaEventDisableTiming);
    }

    // fork point on the (possibly capturing) default stream
    cudaEventRecord(ev0, 0);

    // branch B: CSR build chain
    cudaStreamWaitEvent(sB, ev0, 0);
    zero_kernel<<<(N_NODE2 + 255) / 256, 256, 0, sB>>>(cnt);
    hist_kernel<<<(2 * (N_EDGE / 4) + 255) / 256, 256, 0, sB>>>(
        (const int4*)dst_u2i, (const int4*)dst_i2u, cnt);
    scan1_kernel<<<NBLK_SCAN, 256, 0, sB>>>(cnt, offs, bsum);
    scan2_kernel<<<1, 256, 0, sB>>>(bsum, boff);
    scan3_kernel<<<(N_NODE2 + 255) / 256, 256, 0, sB>>>(offs, boff, cursor);
    cudaEventRecord(evB, sB);

    // branch C: item linear (overlaps user linear's wave tail)
    cudaStreamWaitEvent(sC, ev0, 0);
    linear_attn_kernel<<<N_ITEM / LROWS, 256, 0, sC>>>(feat_item, W_item, b_item, attn_w,
                                                       Wh_item, si_src, si_dst);
    cudaEventRecord(evC, sC);

    // main branch: user linear
    linear_attn_kernel<<<N_USER / LROWS, 256>>>(feat_user, W_user, b_user, attn_w,
                                                Wh_user, su_src, su_dst);

    // join: scatter needs scalars (main, C) + cursor (B)
    cudaStreamWaitEvent(0, evB, 0);
    cudaStreamWaitEvent(0, evC, 0);

    scatter_kernel<<<(2 * (N_EDGE / 2) + 255) / 256, 256>>>(
        (const int2*)src_u2i, (const int2*)dst_u2i,
        (const int2*)src_i2u, (const int2*)dst_i2u,
        su_src, su_dst, si_src, si_dst, cursor, csr);

    agg_kernel<<<((N_NODE2 / 2) * 32 + 255) / 256, 256>>>(offs, csr,
                                                          Wh_user, Wh_item,
                                                          (float2*)out);
}

// round 15
// speedup vs baseline: 1.0035x; 1.0035x over previous
#include <cuda_runtime.h>
#include <cuda_fp16.h>

#define N_USER   100000
#define N_ITEM   100000
#define N_NODE2  200000          // combined dst space: [0,100K)=item(u2i), [100K,200K)=user(i2u)
#define N_EDGE   1600000
#define N_EDGE2  3200000
#define IN_DIM   128
#define OUT_DIM  64
#define NEG_SLOPE 0.01f
#define LROWS    32
#define NBLK_SCAN 196            // ceil(200000/1024)

// ---------------- device scratch (static, no runtime alloc) ----------------
__device__ __half2 g_Wh_user[(size_t)N_USER * 32];   // 12.8 MB
__device__ __half2 g_Wh_item[(size_t)N_ITEM * 32];   // 12.8 MB
__device__ float  g_su_src[N_USER];
__device__ float  g_su_dst[N_USER];
__device__ float  g_si_src[N_ITEM];
__device__ float  g_si_dst[N_ITEM];
__device__ float  g_Wa[512 + 4];     // [u_src 128 | u_dst 128 | i_src 128 | i_dst 128 | b·a terms x4]
__device__ int    g_cnt[N_NODE2];
__device__ int    g_offs[N_NODE2];
__device__ int    g_cursor[N_NODE2];
__device__ int    g_bsum[NBLK_SCAN];
__device__ int    g_boff[NBLK_SCAN];
__device__ float2 g_csr[N_EDGE2];     // packed (src_as_float, ex), 25.6 MB

// ---------------- per-replay reset: degree counters ----------------
__global__ __launch_bounds__(256) void zero_kernel(int* __restrict__ cnt)
{
    int i = blockIdx.x * blockDim.x + threadIdx.x;
    if (i < N_NODE2) cnt[i] = 0;
}

// ---------------- Wa = W @ a (projected attention vectors) + b·a scalars ----
// s = Wh·a = (feat@W + b)·a = feat@(W@a) + b·a  — lets the edge scalars be
// computed WITHOUT Wh, decoupling scatter from the linears.
__global__ __launch_bounds__(256) void wa_kernel(
    const float* __restrict__ W_user, const float* __restrict__ b_user,
    const float* __restrict__ W_item, const float* __restrict__ b_item,
    const float* __restrict__ attn, float* __restrict__ Wa)
{
    int tid = threadIdx.x;          // 256 threads, each 2 outputs
    int k = tid & 127;              // input-dim row
    int half = tid >> 7;            // 0: src vec, 1: dst vec
    const float* a = attn + half * 64;
    float su = 0.f, si = 0.f;
    #pragma unroll 16
    for (int c = 0; c < 64; c++) {
        su = fmaf(W_user[k * 64 + c], a[c], su);
        si = fmaf(W_item[k * 64 + c], a[c], si);
    }
    Wa[half * 128 + k] = su;               // user src/dst
    Wa[256 + half * 128 + k] = si;         // item src/dst
    if (tid < 4) {                          // b·a scalars
        const float* bb = (tid < 2) ? b_user : b_item;
        const float* aa = attn + (tid & 1) * 64;
        float s = 0.f;
        for (int c = 0; c < 64; c++) s = fmaf(bb[c], aa[c], s);
        Wa[512 + tid] = s;                  // [u_src, u_dst, i_src, i_dst]
    }
}

// ---------------- GEMV: s = feat @ Wa + b·a  (warp per node, both tables) ----
__global__ __launch_bounds__(256) void gemv_scalar_kernel(
    const float* __restrict__ feat_user, const float* __restrict__ feat_item,
    const float* __restrict__ Wa,
    float* __restrict__ su_src, float* __restrict__ su_dst,
    float* __restrict__ si_src, float* __restrict__ si_dst)
{
    __shared__ float sWa[516];
    int tid = threadIdx.x;
    sWa[tid] = Wa[tid];
    sWa[256 + tid] = Wa[256 + tid];
    if (tid < 4) sWa[512 + tid] = Wa[512 + tid];
    __syncthreads();

    int node = blockIdx.x * 8 + (tid >> 5);
    int lane = tid & 31;
    if (node >= N_NODE2) return;
    bool user = node < N_USER;
    int n = user ? node : node - N_USER;
    const float* f = (user ? feat_user : feat_item) + (size_t)n * IN_DIM;
    int o = user ? 0 : 256;

    float f0 = f[lane], f1 = f[lane + 32], f2 = f[lane + 64], f3 = f[lane + 96];
    float ps = f0 * sWa[o + lane] + f1 * sWa[o + lane + 32]
             + f2 * sWa[o + lane + 64] + f3 * sWa[o + lane + 96];
    float pd = f0 * sWa[o + 128 + lane] + f1 * sWa[o + 128 + lane + 32]
             + f2 * sWa[o + 128 + lane + 64] + f3 * sWa[o + 128 + lane + 96];
    #pragma unroll
    for (int sh = 16; sh; sh >>= 1) {
        ps += __shfl_xor_sync(0xffffffffu, ps, sh);
        pd += __shfl_xor_sync(0xffffffffu, pd, sh);
    }
    if (lane == 0) {
        if (user) { su_src[n] = ps + sWa[512]; su_dst[n] = pd + sWa[513]; }
        else      { si_src[n] = ps + sWa[514]; si_dst[n] = pd + sWa[515]; }
    }
}

// ------- Wh = feat @ W + b (epilogue removed — scalars come from GEMV) -------
__global__ __launch_bounds__(256) void linear_kernel(
    const float* __restrict__ feat, const float* __restrict__ W,
    const float* __restrict__ b, __half2* __restrict__ Whh)
{
    __shared__ float Ws[IN_DIM * OUT_DIM];   // 32 KB
    __shared__ float fs[LROWS][IN_DIM];      // 16 KB
    int tid = threadIdx.x;

    #pragma unroll
    for (int i = tid; i < IN_DIM * OUT_DIM; i += 256) Ws[i] = W[i];

    int row0 = blockIdx.x * LROWS;
    const float4* fsrc = reinterpret_cast<const float4*>(feat + (size_t)row0 * IN_DIM);
    float4* fdst = reinterpret_cast<float4*>(&fs[0][0]);
    #pragma unroll
    for (int i = tid; i < LROWS * IN_DIM / 4; i += 256) fdst[i] = fsrc[i];
    __syncthreads();

    int cg = tid & 31;   // column pair index
    int rg = tid >> 5;   // row group (4 rows)
    const float2* Ws2 = reinterpret_cast<const float2*>(Ws);
    float2 acc[4] = {{0.f,0.f},{0.f,0.f},{0.f,0.f},{0.f,0.f}};

    #pragma unroll 8
    for (int k = 0; k < IN_DIM; k++) {
        float2 w = Ws2[k * 32 + cg];
        #pragma unroll
        for (int r = 0; r < 4; r++) {
            float f = fs[rg * 4 + r][k];
            acc[r].x = fmaf(f, w.x, acc[r].x);
            acc[r].y = fmaf(f, w.y, acc[r].y);
        }
    }

    float2 b2 = reinterpret_cast<const float2*>(b)[cg];
    #pragma unroll
    for (int r = 0; r < 4; r++) {
        acc[r].x += b2.x; acc[r].y += b2.y;
        Whh[(size_t)(row0 + rg * 4 + r) * 32 + cg] = __float22half2_rn(acc[r]);
    }
}

// ---------------- histogram of dst degrees, both etypes (4 edges/thread) ----
__global__ __launch_bounds__(256) void hist_kernel(const int4* __restrict__ dstA4,
                                                   const int4* __restrict__ dstB4,
                                                   int* __restrict__ cnt)
{
    int i = blockIdx.x * blockDim.x + threadIdx.x;
    const int nq = N_EDGE / 4;
    if (i >= 2 * nq) return;
    bool second = i >= nq;
    int4 d = second ? dstB4[i - nq] : dstA4[i];
    int gbase = second ? N_ITEM : 0;
    atomicAdd(&cnt[gbase + d.x], 1);
    atomicAdd(&cnt[gbase + d.y], 1);
    atomicAdd(&cnt[gbase + d.z], 1);
    atomicAdd(&cnt[gbase + d.w], 1);
}

// ---------------- exclusive scan (3 kernels) ----------------
__global__ __launch_bounds__(256) void scan1_kernel(const int* __restrict__ cnt,
        int* __restrict__ offs, int* __restrict__ bsum)
{
    __shared__ int wsum[8];
    int tid = threadIdx.x;
    int base = blockIdx.x * 1024 + tid * 4;
    int v[4];
    #pragma unroll
    for (int q = 0; q < 4; q++) { int i = base + q; v[q] = (i < N_NODE2) ? cnt[i] : 0; }
    int t = v[0] + v[1] + v[2] + v[3];
    int lane = tid & 31, wid = tid >> 5;
    int inc = t;
    #pragma unroll
    for (int o = 1; o < 32; o <<= 1) { int n = __shfl_up_sync(0xffffffffu, inc, o); if (lane >= o) inc += n; }
    if (lane == 31) wsum[wid] = inc;
    __syncthreads();
    if (wid == 0) {
        int ws = (lane < 8) ? wsum[lane] : 0;
        int winc = ws;
        #pragma unroll
        for (int o = 1; o < 8; o <<= 1) { int n = __shfl_up_sync(0xffffffffu, winc, o); if (lane >= o) winc += n; }
        if (lane < 8) wsum[lane] = winc - ws;          // exclusive warp offsets
        if (lane == 7) bsum[blockIdx.x] = winc;        // block total
    }
    __syncthreads();
    int run = wsum[wid] + (inc - t);
    #pragma unroll
    for (int q = 0; q < 4; q++) { int i = base + q; if (i < N_NODE2) offs[i] = run; run += v[q]; }
}

__global__ __launch_bounds__(256) void scan2_kernel(const int* __restrict__ bsum,
                                                    int* __restrict__ boff)
{
    __shared__ int wsum[8];
    int tid = threadIdx.x;
    int v = (tid < NBLK_SCAN) ? bsum[tid] : 0;
    int lane = tid & 31, wid = tid >> 5;
    int inc = v;
    #pragma unroll
    for (int o = 1; o < 32; o <<= 1) { int n = __shfl_up_sync(0xffffffffu, inc, o); if (lane >= o) inc += n; }
    if (lane == 31) wsum[wid] = inc;
    __syncthreads();
    if (wid == 0) {
        int ws = (lane < 8) ? wsum[lane] : 0;
        int winc = ws;
        #pragma unroll
        for (int o = 1; o < 8; o <<= 1) { int n = __shfl_up_sync(0xffffffffu, winc, o); if (lane >= o) winc += n; }
        if (lane < 8) wsum[lane] = winc - ws;
    }
    __syncthreads();
    if (tid < NBLK_SCAN) boff[tid] = wsum[wid] + (inc - v);
}

__global__ __launch_bounds__(256) void scan3_kernel(int* __restrict__ offs,
        const int* __restrict__ boff, int* __restrict__ cursor)
{
    int i = blockIdx.x * blockDim.x + threadIdx.x;
    if (i >= N_NODE2) return;
    int o = offs[i] + boff[i >> 10];
    offs[i] = o;
    cursor[i] = o;
}

// --------- scatter (both etypes, 2 edges/thread): csr[pos] = (src, ex) ---------
__global__ __launch_bounds__(256) void scatter_kernel(
    const int2* __restrict__ srcA2, const int2* __restrict__ dstA2,
    const int2* __restrict__ srcB2, const int2* __restrict__ dstB2,
    const float* __restrict__ su_src, const float* __restrict__ su_dst,
    const float* __restrict__ si_src, const float* __restrict__ si_dst,
    int* __restrict__ cursor, float2* __restrict__ csr)
{
    int t = blockIdx.x * blockDim.x + threadIdx.x;
    const int nh = N_EDGE / 2;
    if (t >= 2 * nh) return;
    bool second = t >= nh;
    int e2 = second ? t - nh : t;
    int2 s2 = second ? srcB2[e2] : srcA2[e2];
    int2 d2 = second ? dstB2[e2] : dstA2[e2];
    const float* ssrc = second ? si_src : su_src;
    const float* sdst = second ? su_dst : si_dst;
    int gbase = second ? N_ITEM : 0;

    float vs0 = ssrc[s2.x], vs1 = ssrc[s2.y];
    float vd0 = sdst[d2.x], vd1 = sdst[d2.y];
    float v0 = vs0 + vd0;  v0 = v0 > 0.f ? v0 : NEG_SLOPE * v0;
    float v1 = vs1 + vd1;  v1 = v1 > 0.f ? v1 : NEG_SLOPE * v1;
    float ex0 = __expf(v0), ex1 = __expf(v1);

    int pos0 = atomicAdd(&cursor[gbase + d2.x], 1);
    int pos1 = atomicAdd(&cursor[gbase + d2.y], 1);
    csr[pos0] = make_float2(__int_as_float(s2.x), ex0);
    csr[pos1] = make_float2(__int_as_float(s2.y), ex1);
}

// --------- aggregate: warp per dst node; unroll-8; fp16 gathers (measured-best) ---------
__global__ __launch_bounds__(256) void agg_kernel(
    const int* __restrict__ offs, const float2* __restrict__ csr,
    const __half2* __restrict__ Whu, const __half2* __restrict__ Whi,
    float2* __restrict__ out2)
{
    int g = (blockIdx.x * 256 + threadIdx.x) >> 5;
    int lane = threadIdx.x & 31;
    if (g >= N_NODE2) return;

    int beg = offs[g];
    int end = (g == N_NODE2 - 1) ? N_EDGE2 : offs[g + 1];
    const __half2* Wh2 = (g < N_ITEM) ? Whu : Whi;             // item-dst <- user src
    int orow = (g < N_ITEM) ? (N_USER + g) : (g - N_ITEM);

    float2 acc = make_float2(0.f, 0.f);
    float den = 0.f;

    for (int k0 = beg; k0 < end; k0 += 32) {
        int k = k0 + lane;
        float2 p = (k < end) ? csr[k] : make_float2(0.f, 0.f);  // pad: s=0(valid), ex=0
        int   s  = __float_as_int(p.x);
        float ex = p.y;
        int m = end - k0; if (m > 32) m = 32;
        for (int j0 = 0; j0 < m; j0 += 8) {
            #pragma unroll
            for (int jj = 0; jj < 8; jj++) {
                int   sj = __shfl_sync(0xffffffffu, s,  j0 + jj);
                float ej = __shfl_sync(0xffffffffu, ex, j0 + jj);
                if (ej != 0.f) {
                    float2 z = __half22float2(Wh2[(size_t)sj * 32 + lane]);
                    acc.x = fmaf(ej, z.x, acc.x);
                    acc.y = fmaf(ej, z.y, acc.y);
                    den += ej;
                }
            }
        }
    }
    if (end > beg) {
        float inv = 1.f / den;
        acc.x *= inv; acc.y *= inv;
    }
    out2[(size_t)orow * 32 + lane] = acc;
}

// ---------------- launch: decoupled-scalar pipelined schedule ----------------
// s = feat@(W@a) + b·a makes the edge scalars independent of the linears, so
// scatter moves OFF the critical path:
//   sB: zero->hist->scan1/2/3 ----\
//   sD: Wa -> GEMV scalars --------+-> sB: scatter -> evS
//   sC: linear_item    main: linear_user
//   main: wait(evS, evC) -> agg
extern "C" void kernel_launch(void* const* d_in, const int* in_sizes, int n_in,
                              void* d_out, int out_size)
{
    const float* feat_user = (const float*)d_in[0];
    const float* feat_item = (const float*)d_in[1];
    const float* W_user    = (const float*)d_in[2];
    const float* b_user    = (const float*)d_in[3];
    const float* W_item    = (const float*)d_in[4];
    const float* b_item    = (const float*)d_in[5];
    const float* attn_w    = (const float*)d_in[6];
    const int*   src_u2i   = (const int*)d_in[7];
    const int*   dst_u2i   = (const int*)d_in[8];
    const int*   src_i2u   = (const int*)d_in[9];
    const int*   dst_i2u   = (const int*)d_in[10];
    float* out = (float*)d_out;

    // true DEVICE addresses of __device__ globals (host-shadow/ATS trap!)
    __half2 *Wh_user, *Wh_item;
    float *su_src, *su_dst, *si_src, *si_dst, *Wa;
    float2 *csr;
    int *cnt, *offs, *cursor, *bsum, *boff;
    cudaGetSymbolAddress((void**)&Wh_user, g_Wh_user);
    cudaGetSymbolAddress((void**)&Wh_item, g_Wh_item);
    cudaGetSymbolAddress((void**)&su_src,  g_su_src);
    cudaGetSymbolAddress((void**)&su_dst,  g_su_dst);
    cudaGetSymbolAddress((void**)&si_src,  g_si_src);
    cudaGetSymbolAddress((void**)&si_dst,  g_si_dst);
    cudaGetSymbolAddress((void**)&Wa,      g_Wa);
    cudaGetSymbolAddress((void**)&cnt,     g_cnt);
    cudaGetSymbolAddress((void**)&offs,    g_offs);
    cudaGetSymbolAddress((void**)&cursor,  g_cursor);
    cudaGetSymbolAddress((void**)&bsum,    g_bsum);
    cudaGetSymbolAddress((void**)&boff,    g_boff);
    cudaGetSymbolAddress((void**)&csr,     g_csr);

    static cudaStream_t sB = nullptr, sC = nullptr, sD = nullptr;
    static cudaEvent_t ev0 = nullptr, evG = nullptr, evS = nullptr, evC = nullptr;
    if (sB == nullptr) {
        cudaStreamCreateWithFlags(&sB, cudaStreamNonBlocking);
        cudaStreamCreateWithFlags(&sC, cudaStreamNonBlocking);
        cudaStreamCreateWithFlags(&sD, cudaStreamNonBlocking);
        cudaEventCreateWithFlags(&ev0, cudaEventDisableTiming);
        cudaEventCreateWithFlags(&evG, cudaEventDisableTiming);
        cudaEventCreateWithFlags(&evS, cudaEventDisableTiming);
        cudaEventCreateWithFlags(&evC, cudaEventDisableTiming);
    }

    // fork point on the (possibly capturing) default stream
    cudaEventRecord(ev0, 0);

    // branch D: projected attention scalars (independent of linears)
    cudaStreamWaitEvent(sD, ev0, 0);
    wa_kernel<<<1, 256, 0, sD>>>(W_user, b_user, W_item, b_item, attn_w, Wa);
    gemv_scalar_kernel<<<(N_NODE2 + 7) / 8, 256, 0, sD>>>(
        feat_user, feat_item, Wa, su_src, su_dst, si_src, si_dst);
    cudaEventRecord(evG, sD);

    // branch B: CSR build chain, then scatter (needs scalars from D)
    cudaStreamWaitEvent(sB, ev0, 0);
    zero_kernel<<<(N_NODE2 + 255) / 256, 256, 0, sB>>>(cnt);
    hist_kernel<<<(2 * (N_EDGE / 4) + 255) / 256, 256, 0, sB>>>(
        (const int4*)dst_u2i, (const int4*)dst_i2u, cnt);
    scan1_kernel<<<NBLK_SCAN, 256, 0, sB>>>(cnt, offs, bsum);
    scan2_kernel<<<1, 256, 0, sB>>>(bsum, boff);
    scan3_kernel<<<(N_NODE2 + 255) / 256, 256, 0, sB>>>(offs, boff, cursor);
    cudaStreamWaitEvent(sB, evG, 0);
    scatter_kernel<<<(2 * (N_EDGE / 2) + 255) / 256, 256, 0, sB>>>(
        (const int2*)src_u2i, (const int2*)dst_u2i,
        (const int2*)src_i2u, (const int2*)dst_i2u,
        su_src, su_dst, si_src, si_dst, cursor, csr);
    cudaEventRecord(evS, sB);

    // branch C: item linear
    cudaStreamWaitEvent(sC, ev0, 0);
    linear_kernel<<<N_ITEM / LROWS, 256, 0, sC>>>(feat_item, W_item, b_item, Wh_item);
    cudaEventRecord(evC, sC);

    // main branch: user linear
    linear_kernel<<<N_USER / LROWS, 256>>>(feat_user, W_user, b_user, Wh_user);

    // join: agg needs Wh (main, C) + CSR (B)
    cudaStreamWaitEvent(0, evS, 0);
    cudaStreamWaitEvent(0, evC, 0);

    agg_kernel<<<(N_NODE2 * 32 + 255) / 256, 256>>>(offs, csr,
                                                    Wh_user, Wh_item,
                                                    (float2*)out);
}

// round 16
// speedup vs baseline: 1.0726x; 1.0688x over previous
#include <cuda_runtime.h>

#define N_USER   100000
#define N_ITEM   100000
#define N_NODE2  200000          // combined dst space: [0,100K)=item(u2i), [100K,200K)=user(i2u)
#define N_EDGE   1600000
#define N_EDGE2  3200000
#define IN_DIM   128
#define OUT_DIM  64
#define NEG_SLOPE 0.01f
#define LROWS    32
#define NBLK_SCAN 196            // ceil(200000/1024)

// ---------------- device scratch (static, no runtime alloc) ----------------
__device__ float  g_Wh_user[(size_t)N_USER * OUT_DIM];   // 25.6 MB
__device__ float  g_Wh_item[(size_t)N_ITEM * OUT_DIM];   // 25.6 MB
__device__ float  g_su_src[N_USER];
__device__ float  g_su_dst[N_USER];
__device__ float  g_si_src[N_ITEM];
__device__ float  g_si_dst[N_ITEM];
__device__ int    g_cnt[N_NODE2];
__device__ int    g_offs[N_NODE2];
__device__ int    g_cursor[N_NODE2];
__device__ int    g_bsum[NBLK_SCAN];
__device__ int    g_boff[NBLK_SCAN];
__device__ float2 g_csr[N_EDGE2];     // packed (src_as_float, ex), 25.6 MB

// ---------------- per-replay reset: degree counters ----------------
__global__ __launch_bounds__(256) void zero_kernel(int* __restrict__ cnt)
{
    int i = blockIdx.x * blockDim.x + threadIdx.x;
    if (i < N_NODE2) cnt[i] = 0;
}

// ------- Wh = feat @ W + b fused with s_src/s_dst epilogue -------
// (round-10 measured-best: thread = 2 cols x 4 rows; at FP32 FMA floor)
__global__ __launch_bounds__(256) void linear_attn_kernel(
    const float* __restrict__ feat, const float* __restrict__ W,
    const float* __restrict__ b, const float* __restrict__ attn,
    float* __restrict__ Wh, float* __restrict__ s_src, float* __restrict__ s_dst)
{
    __shared__ float Ws[IN_DIM * OUT_DIM];   // 32 KB
    __shared__ float fs[LROWS][IN_DIM];      // 16 KB (reused for Wh tile)
    int tid = threadIdx.x;

    #pragma unroll
    for (int i = tid; i < IN_DIM * OUT_DIM; i += 256) Ws[i] = W[i];

    int row0 = blockIdx.x * LROWS;
    const float4* fsrc = reinterpret_cast<const float4*>(feat + (size_t)row0 * IN_DIM);
    float4* fdst = reinterpret_cast<float4*>(&fs[0][0]);
    #pragma unroll
    for (int i = tid; i < LROWS * IN_DIM / 4; i += 256) fdst[i] = fsrc[i];
    __syncthreads();

    int cg = tid & 31;   // column pair index
    int rg = tid >> 5;   // row group (4 rows)
    const float2* Ws2 = reinterpret_cast<const float2*>(Ws);
    float2 acc[4] = {{0.f,0.f},{0.f,0.f},{0.f,0.f},{0.f,0.f}};

    #pragma unroll 8
    for (int k = 0; k < IN_DIM; k++) {
        float2 w = Ws2[k * 32 + cg];
        #pragma unroll
        for (int r = 0; r < 4; r++) {
            float f = fs[rg * 4 + r][k];
            acc[r].x = fmaf(f, w.x, acc[r].x);
            acc[r].y = fmaf(f, w.y, acc[r].y);
        }
    }

    float2 b2 = reinterpret_cast<const float2*>(b)[cg];
    __syncthreads();   // done reading fs; reuse as Wh tile
    float2* sWh2 = reinterpret_cast<float2*>(&fs[0][0]);   // [32][32] float2
    #pragma unroll
    for (int r = 0; r < 4; r++) {
        acc[r].x += b2.x; acc[r].y += b2.y;
        int row = rg * 4 + r;
        reinterpret_cast<float2*>(Wh)[(size_t)(row0 + row) * 32 + cg] = acc[r];
        sWh2[row * 32 + cg] = acc[r];
    }
    __syncthreads();

    // epilogue: 8 warps x 4 rows
    int wid = tid >> 5, lane = tid & 31;
    float a0 = attn[lane],      a1 = attn[lane + 32];
    float c0 = attn[64 + lane], c1 = attn[96 + lane];
    const float* sWh = &fs[0][0];
    #pragma unroll
    for (int rr = 0; rr < 4; rr++) {
        int row = wid * 4 + rr;
        float v0 = sWh[row * 64 + lane];
        float v1 = sWh[row * 64 + lane + 32];
        float ps = fmaf(v0, a0, v1 * a1);
        float pd = fmaf(v0, c0, v1 * c1);
        #pragma unroll
        for (int o = 16; o; o >>= 1) {
            ps += __shfl_xor_sync(0xffffffffu, ps, o);
            pd += __shfl_xor_sync(0xffffffffu, pd, o);
        }
        if (lane == 0) { s_src[row0 + row] = ps; s_dst[row0 + row] = pd; }
    }
}

// ---------------- histogram of dst degrees, both etypes (4 edges/thread) ----
__global__ __launch_bounds__(256) void hist_kernel(const int4* __restrict__ dstA4,
                                                   const int4* __restrict__ dstB4,
                                                   int* __restrict__ cnt)
{
    int i = blockIdx.x * blockDim.x + threadIdx.x;
    const int nq = N_EDGE / 4;
    if (i >= 2 * nq) return;
    bool second = i >= nq;
    int4 d = second ? dstB4[i - nq] : dstA4[i];
    int gbase = second ? N_ITEM : 0;
    atomicAdd(&cnt[gbase + d.x], 1);
    atomicAdd(&cnt[gbase + d.y], 1);
    atomicAdd(&cnt[gbase + d.z], 1);
    atomicAdd(&cnt[gbase + d.w], 1);
}

// ---------------- exclusive scan (3 kernels) ----------------
__global__ __launch_bounds__(256) void scan1_kernel(const int* __restrict__ cnt,
        int* __restrict__ offs, int* __restrict__ bsum)
{
    __shared__ int wsum[8];
    int tid = threadIdx.x;
    int base = blockIdx.x * 1024 + tid * 4;
    int v[4];
    #pragma unroll
    for (int q = 0; q < 4; q++) { int i = base + q; v[q] = (i < N_NODE2) ? cnt[i] : 0; }
    int t = v[0] + v[1] + v[2] + v[3];
    int lane = tid & 31, wid = tid >> 5;
    int inc = t;
    #pragma unroll
    for (int o = 1; o < 32; o <<= 1) { int n = __shfl_up_sync(0xffffffffu, inc, o); if (lane >= o) inc += n; }
    if (lane == 31) wsum[wid] = inc;
    __syncthreads();
    if (wid == 0) {
        int ws = (lane < 8) ? wsum[lane] : 0;
        int winc = ws;
        #pragma unroll
        for (int o = 1; o < 8; o <<= 1) { int n = __shfl_up_sync(0xffffffffu, winc, o); if (lane >= o) winc += n; }
        if (lane < 8) wsum[lane] = winc - ws;          // exclusive warp offsets
        if (lane == 7) bsum[blockIdx.x] = winc;        // block total
    }
    __syncthreads();
    int run = wsum[wid] + (inc - t);
    #pragma unroll
    for (int q = 0; q < 4; q++) { int i = base + q; if (i < N_NODE2) offs[i] = run; run += v[q]; }
}

__global__ __launch_bounds__(256) void scan2_kernel(const int* __restrict__ bsum,
                                                    int* __restrict__ boff)
{
    __shared__ int wsum[8];
    int tid = threadIdx.x;
    int v = (tid < NBLK_SCAN) ? bsum[tid] : 0;
    int lane = tid & 31, wid = tid >> 5;
    int inc = v;
    #pragma unroll
    for (int o = 1; o < 32; o <<= 1) { int n = __shfl_up_sync(0xffffffffu, inc, o); if (lane >= o) inc += n; }
    if (lane == 31) wsum[wid] = inc;
    __syncthreads();
    if (wid == 0) {
        int ws = (lane < 8) ? wsum[lane] : 0;
        int winc = ws;
        #pragma unroll
        for (int o = 1; o < 8; o <<= 1) { int n = __shfl_up_sync(0xffffffffu, winc, o); if (lane >= o) winc += n; }
        if (lane < 8) wsum[lane] = winc - ws;
    }
    __syncthreads();
    if (tid < NBLK_SCAN) boff[tid] = wsum[wid] + (inc - v);
}

__global__ __launch_bounds__(256) void scan3_kernel(int* __restrict__ offs,
        const int* __restrict__ boff, int* __restrict__ cursor)
{
    int i = blockIdx.x * blockDim.x + threadIdx.x;
    if (i >= N_NODE2) return;
    int o = offs[i] + boff[i >> 10];
    offs[i] = o;
    cursor[i] = o;
}

// --------- scatter (both etypes, 2 edges/thread): csr[pos] = (src, ex) ---------
__global__ __launch_bounds__(256) void scatter_kernel(
    const int2* __restrict__ srcA2, const int2* __restrict__ dstA2,
    const int2* __restrict__ srcB2, const int2* __restrict__ dstB2,
    const float* __restrict__ su_src, const float* __restrict__ su_dst,
    const float* __restrict__ si_src, const float* __restrict__ si_dst,
    int* __restrict__ cursor, float2* __restrict__ csr)
{
    int t = blockIdx.x * blockDim.x + threadIdx.x;
    const int nh = N_EDGE / 2;
    if (t >= 2 * nh) return;
    bool second = t >= nh;
    int e2 = second ? t - nh : t;
    int2 s2 = second ? srcB2[e2] : srcA2[e2];
    int2 d2 = second ? dstB2[e2] : dstA2[e2];
    const float* ssrc = second ? si_src : su_src;
    const float* sdst = second ? su_dst : si_dst;
    int gbase = second ? N_ITEM : 0;

    float vs0 = ssrc[s2.x], vs1 = ssrc[s2.y];
    float vd0 = sdst[d2.x], vd1 = sdst[d2.y];
    float v0 = vs0 + vd0;  v0 = v0 > 0.f ? v0 : NEG_SLOPE * v0;
    float v1 = vs1 + vd1;  v1 = v1 > 0.f ? v1 : NEG_SLOPE * v1;
    float ex0 = __expf(v0), ex1 = __expf(v1);

    int pos0 = atomicAdd(&cursor[gbase + d2.x], 1);
    int pos1 = atomicAdd(&cursor[gbase + d2.y], 1);
    csr[pos0] = make_float2(__int_as_float(s2.x), ex0);
    csr[pos1] = make_float2(__int_as_float(s2.y), ex1);
}

// --------- aggregate: warp per dst node; unroll-8 (round-10 body) --------
// 64-thread blocks: CTA retire = max over 2 warps (not 8) of Poisson-degree
// work -> smaller straggler quantum, finer CLC backfill. Body unchanged.
__global__ __launch_bounds__(64) void agg_kernel(
    const int* __restrict__ offs, const float2* __restrict__ csr,
    const float2* __restrict__ Whu2, const float2* __restrict__ Whi2,
    float2* __restrict__ out2)
{
    int g = (blockIdx.x * 64 + threadIdx.x) >> 5;
    int lane = threadIdx.x & 31;
    if (g >= N_NODE2) return;

    int beg = offs[g];
    int end = (g == N_NODE2 - 1) ? N_EDGE2 : offs[g + 1];
    const float2* Wh2 = (g < N_ITEM) ? Whu2 : Whi2;            // item-dst <- user src
    int orow = (g < N_ITEM) ? (N_USER + g) : (g - N_ITEM);

    float2 acc = make_float2(0.f, 0.f);
    float den = 0.f;

    for (int k0 = beg; k0 < end; k0 += 32) {
        int k = k0 + lane;
        float2 p = (k < end) ? csr[k] : make_float2(0.f, 0.f);  // pad: s=0(valid), ex=0
        int   s  = __float_as_int(p.x);
        float ex = p.y;
        int m = end - k0; if (m > 32) m = 32;
        for (int j0 = 0; j0 < m; j0 += 8) {
            #pragma unroll
            for (int jj = 0; jj < 8; jj++) {
                int   sj = __shfl_sync(0xffffffffu, s,  j0 + jj);
                float ej = __shfl_sync(0xffffffffu, ex, j0 + jj);
                if (ej != 0.f) {
                    float2 z = Wh2[(size_t)sj * 32 + lane];
                    acc.x = fmaf(ej, z.x, acc.x);
                    acc.y = fmaf(ej, z.y, acc.y);
                    den += ej;
                }
            }
        }
    }
    if (end > beg) {
        float inv = 1.f / den;
        acc.x *= inv; acc.y *= inv;
    }
    out2[(size_t)orow * 32 + lane] = acc;
}

// ---------------- launch: forked-capture schedule (round-10 measured-best) ----------------
extern "C" void kernel_launch(void* const* d_in, const int* in_sizes, int n_in,
                              void* d_out, int out_size)
{
    const float* feat_user = (const float*)d_in[0];
    const float* feat_item = (const float*)d_in[1];
    const float* W_user    = (const float*)d_in[2];
    const float* b_user    = (const float*)d_in[3];
    const float* W_item    = (const float*)d_in[4];
    const float* b_item    = (const float*)d_in[5];
    const float* attn_w    = (const float*)d_in[6];
    const int*   src_u2i   = (const int*)d_in[7];
    const int*   dst_u2i   = (const int*)d_in[8];
    const int*   src_i2u   = (const int*)d_in[9];
    const int*   dst_i2u   = (const int*)d_in[10];
    float* out = (float*)d_out;

    // true DEVICE addresses of __device__ globals (host-shadow/ATS trap!)
    float *Wh_user, *Wh_item, *su_src, *su_dst, *si_src, *si_dst;
    float2 *csr;
    int *cnt, *offs, *cursor, *bsum, *boff;
    cudaGetSymbolAddress((void**)&Wh_user, g_Wh_user);
    cudaGetSymbolAddress((void**)&Wh_item, g_Wh_item);
    cudaGetSymbolAddress((void**)&su_src,  g_su_src);
    cudaGetSymbolAddress((void**)&su_dst,  g_su_dst);
    cudaGetSymbolAddress((void**)&si_src,  g_si_src);
    cudaGetSymbolAddress((void**)&si_dst,  g_si_dst);
    cudaGetSymbolAddress((void**)&cnt,     g_cnt);
    cudaGetSymbolAddress((void**)&offs,    g_offs);
    cudaGetSymbolAddress((void**)&cursor,  g_cursor);
    cudaGetSymbolAddress((void**)&bsum,    g_bsum);
    cudaGetSymbolAddress((void**)&boff,    g_boff);
    cudaGetSymbolAddress((void**)&csr,     g_csr);

    static cudaStream_t sB = nullptr, sC = nullptr;
    static cudaEvent_t ev0 = nullptr, evB = nullptr, evC = nullptr;
    if (sB == nullptr) {
        cudaStreamCreateWithFlags(&sB, cudaStreamNonBlocking);
        cudaStreamCreateWithFlags(&sC, cudaStreamNonBlocking);
        cudaEventCreateWithFlags(&ev0, cudaEventDisableTiming);
        cudaEventCreateWithFlags(&evB, cudaEventDisableTiming);
        cudaEventCreateWithFlags(&evC, cudaEventDisableTiming);
    }

    // fork point on the (possibly capturing) default stream
    cudaEventRecord(ev0, 0);

    // branch B: CSR build chain
    cudaStreamWaitEvent(sB, ev0, 0);
    zero_kernel<<<(N_NODE2 + 255) / 256, 256, 0, sB>>>(cnt);
    hist_kernel<<<(2 * (N_EDGE / 4) + 255) / 256, 256, 0, sB>>>(
        (const int4*)dst_u2i, (const int4*)dst_i2u, cnt);
    scan1_kernel<<<NBLK_SCAN, 256, 0, sB>>>(cnt, offs, bsum);
    scan2_kernel<<<1, 256, 0, sB>>>(bsum, boff);
    scan3_kernel<<<(N_NODE2 + 255) / 256, 256, 0, sB>>>(offs, boff, cursor);
    cudaEventRecord(evB, sB);

    // branch C: item linear (overlaps user linear's wave tail)
    cudaStreamWaitEvent(sC, ev0, 0);
    linear_attn_kernel<<<N_ITEM / LROWS, 256, 0, sC>>>(feat_item, W_item, b_item, attn_w,
                                                       Wh_item, si_src, si_dst);
    cudaEventRecord(evC, sC);

    // main branch: user linear
    linear_attn_kernel<<<N_USER / LROWS, 256>>>(feat_user, W_user, b_user, attn_w,
                                                Wh_user, su_src, su_dst);

    // join: scatter needs scalars (main, C) + cursor (B)
    cudaStreamWaitEvent(0, evB, 0);
    cudaStreamWaitEvent(0, evC, 0);

    scatter_kernel<<<(2 * (N_EDGE / 2) + 255) / 256, 256>>>(
        (const int2*)src_u2i, (const int2*)dst_u2i,
        (const int2*)src_i2u, (const int2*)dst_i2u,
        su_src, su_dst, si_src, si_dst, cursor, csr);

    agg_kernel<<<(N_NODE2 * 32 + 63) / 64, 64>>>(offs, csr,
                                                 (const float2*)Wh_user,
                                                 (const float2*)Wh_item,
                                                 (float2*)out);
}